// round 4
// baseline (speedup 1.0000x reference)
#include <cuda_runtime.h>

// Problem constants
#define S_DIM 256
#define B_DIM 128
#define D_DIM 768
#define L_DIM 200
#define V_DIM 8
#define M_DIM (S_DIM * B_DIM)   // 32768 rows (s*128 + b)
#define N_DIM (L_DIM * V_DIM)   // 1600 cols (l*8 + v)

// GEMM tiling
#define BM 128
#define BN 64
#define BK 32
#define AS_STRIDE (BM + 4)      // 132 floats per k-row (transposed A tile)
#define BS_STRIDE (BN + 4)      // 68 floats per k-row (transposed B tile)

// Scratch for norms (no allocation allowed)
__device__ float g_ne[M_DIM];
__device__ float g_nl[N_DIM];

typedef unsigned long long ull;

// ---- packed f32x2 helpers (sm_100+ PTX; ptxas never emits these from C++) ----
__device__ __forceinline__ void fma2(ull& d, ull a, ull b) {
    asm("fma.rn.f32x2 %0, %1, %2, %0;" : "+l"(d) : "l"(a), "l"(b));
}
__device__ __forceinline__ ull pack2(float lo, float hi) {
    ull r;
    asm("mov.b64 %0, {%1, %2};" : "=l"(r) : "f"(lo), "f"(hi));
    return r;
}
__device__ __forceinline__ void unpack2(ull p, float& lo, float& hi) {
    asm("mov.b64 {%0, %1}, %2;" : "=f"(lo), "=f"(hi) : "l"(p));
}

// Sign-aware float atomic max (works for mixed signs; values in [-1, 1])
__device__ __forceinline__ void atomicMaxF(float* addr, float v) {
    if (v >= 0.0f) {
        atomicMax((int*)addr, __float_as_int(v));
    } else {
        atomicMin((unsigned int*)addr, __float_as_uint(v));
    }
}

__global__ void init_out_kernel(float* out) {
    int i = blockIdx.x * blockDim.x + threadIdx.x;
    if (i < B_DIM * L_DIM) out[i] = -1.0f;
}

// One warp per row: L2 norm over the D=768 feature dim.
__global__ void row_norms_kernel(const float* __restrict__ x,
                                 float* __restrict__ out, int rows) {
    int w = (blockIdx.x * blockDim.x + threadIdx.x) >> 5;
    int lane = threadIdx.x & 31;
    if (w >= rows) return;
    const float4* p = reinterpret_cast<const float4*>(x + (size_t)w * D_DIM);
    float s = 0.0f;
#pragma unroll
    for (int i = 0; i < D_DIM / 4 / 32; i++) {       // 6 iterations
        float4 v = p[lane + i * 32];
        s += v.x * v.x + v.y * v.y + v.z * v.z + v.w * v.w;
    }
#pragma unroll
    for (int o = 16; o > 0; o >>= 1) s += __shfl_xor_sync(0xffffffffu, s, o);
    if (lane == 0) out[w] = sqrtf(s);
}

// Fused GEMM (A[M,K] * B[N,K]^T) + cosine + max-over-(s,v) reduction into out[B,L].
// Tile (by, bx): rows m0..m0+127 share one s; local row r == batch b.
// Cols n0..n0+63 cover 8 full l-groups of 8 v each.
__global__ __launch_bounds__(256, 2)
void gemm_cosmax_kernel(const float* __restrict__ A,
                        const float* __restrict__ Bm,
                        float* __restrict__ out) {
    __shared__ float As[BK][AS_STRIDE];   // [k][row]  (transposed)
    __shared__ float Bs[BK][BS_STRIDE];   // [k][col]  (transposed)

    const int tid = threadIdx.x;
    const int tx  = tid & 15;   // 16 col-groups of 4
    const int ty  = tid >> 4;   // 16 row-groups of 8
    const int m0  = blockIdx.y * BM;
    const int n0  = blockIdx.x * BN;

    float4 pa[4];   // prefetch regs: A tile = 128x32 = 1024 f4 / 256 thr = 4
    float4 pb[2];   // B tile = 64x32 = 512 f4 / 256 thr = 2

    auto loadG = [&](int kt) {
#pragma unroll
        for (int j = 0; j < 4; j++) {
            int f = j * 256 + tid;
            int r = f >> 3, q = f & 7;
            pa[j] = *reinterpret_cast<const float4*>(
                A + (size_t)(m0 + r) * D_DIM + kt + q * 4);
        }
#pragma unroll
        for (int j = 0; j < 2; j++) {
            int f = j * 256 + tid;
            int n = f >> 3, q = f & 7;
            pb[j] = *reinterpret_cast<const float4*>(
                Bm + (size_t)(n0 + n) * D_DIM + kt + q * 4);
        }
    };
    auto storeS = [&]() {
#pragma unroll
        for (int j = 0; j < 4; j++) {
            int f = j * 256 + tid;
            int r = f >> 3, q = f & 7;
            As[q * 4 + 0][r] = pa[j].x;
            As[q * 4 + 1][r] = pa[j].y;
            As[q * 4 + 2][r] = pa[j].z;
            As[q * 4 + 3][r] = pa[j].w;
        }
#pragma unroll
        for (int j = 0; j < 2; j++) {
            int f = j * 256 + tid;
            int n = f >> 3, q = f & 7;
            Bs[q * 4 + 0][n] = pb[j].x;
            Bs[q * 4 + 1][n] = pb[j].y;
            Bs[q * 4 + 2][n] = pb[j].z;
            Bs[q * 4 + 3][n] = pb[j].w;
        }
    };

    // acc[i][j]: row-pair i (rows ty*8+2i, ty*8+2i+1), col j (n0+tx*4+j)
    ull acc[4][4];
#pragma unroll
    for (int i = 0; i < 4; i++)
#pragma unroll
        for (int j = 0; j < 4; j++) acc[i][j] = 0ull;   // bits of (0.f, 0.f)

    loadG(0);
    storeS();
    __syncthreads();

    for (int kt = 0; kt < D_DIM; kt += BK) {
        const bool nxt = (kt + BK) < D_DIM;
        if (nxt) loadG(kt + BK);    // global prefetch overlaps with compute below

#pragma unroll
        for (int kk = 0; kk < BK; kk++) {
            // 8 consecutive rows at this k -> 4 zero-cost f32x2 pairs
            ulonglong2 a01 =
                *reinterpret_cast<const ulonglong2*>(&As[kk][ty * 8]);
            ulonglong2 a23 =
                *reinterpret_cast<const ulonglong2*>(&As[kk][ty * 8 + 4]);
            float4 b = *reinterpret_cast<const float4*>(&Bs[kk][tx * 4]);
            ull ap[4] = {a01.x, a01.y, a23.x, a23.y};
            ull bd[4] = {pack2(b.x, b.x), pack2(b.y, b.y),
                         pack2(b.z, b.z), pack2(b.w, b.w)};
#pragma unroll
            for (int i = 0; i < 4; i++)
#pragma unroll
                for (int j = 0; j < 4; j++) fma2(acc[i][j], ap[i], bd[j]);
        }
        __syncthreads();
        if (nxt) {
            storeS();
            __syncthreads();
        }
    }

    // ---- epilogue: cosine + max over v (4 here + 4 in partner lane) ----
    float nl_c[4];
#pragma unroll
    for (int j = 0; j < 4; j++) nl_c[j] = g_nl[n0 + tx * 4 + j];
    const int l = (n0 + tx * 4) >> 3;   // global label index; tx pair shares l

#pragma unroll
    for (int i = 0; i < 4; i++) {
        int r0 = ty * 8 + i * 2;                    // local row == batch b
        float ne0 = g_ne[m0 + r0];
        float ne1 = g_ne[m0 + r0 + 1];
        float mx0 = -1.0f, mx1 = -1.0f;
#pragma unroll
        for (int j = 0; j < 4; j++) {
            float lo, hi;
            unpack2(acc[i][j], lo, hi);
            mx0 = fmaxf(mx0, lo / fmaxf(ne0 * nl_c[j], 1e-8f));
            mx1 = fmaxf(mx1, hi / fmaxf(ne1 * nl_c[j], 1e-8f));
        }
        // partner lane (tx^1) holds the other 4 v's of the same l
        float o0 = __shfl_xor_sync(0xffffffffu, mx0, 1);
        float o1 = __shfl_xor_sync(0xffffffffu, mx1, 1);
        mx0 = fmaxf(mx0, o0);
        mx1 = fmaxf(mx1, o1);
        if ((tx & 1) == 0) {
            atomicMaxF(&out[r0 * L_DIM + l], mx0);
            atomicMaxF(&out[(r0 + 1) * L_DIM + l], mx1);
        }
    }
}

extern "C" void kernel_launch(void* const* d_in, const int* in_sizes, int n_in,
                              void* d_out, int out_size) {
    const float* embed = (const float*)d_in[0];        // [256,128,768]
    const float* label = (const float*)d_in[1];        // [200,8,768]
    float* out = (float*)d_out;                        // [128,200]

    float* d_ne;
    float* d_nl;
    cudaGetSymbolAddress((void**)&d_ne, g_ne);
    cudaGetSymbolAddress((void**)&d_nl, g_nl);

    init_out_kernel<<<(B_DIM * L_DIM + 255) / 256, 256>>>(out);
    row_norms_kernel<<<M_DIM / 8, 256>>>(embed, d_ne, M_DIM);  // 8 warps/blk
    row_norms_kernel<<<N_DIM / 8, 256>>>(label, d_nl, N_DIM);

    dim3 grid(N_DIM / BN, M_DIM / BM);   // (25, 256) = 6400 CTAs
    gemm_cosmax_kernel<<<grid, 256>>>(embed, label, out);
}

// round 6
// speedup vs baseline: 6.6414x; 6.6414x over previous
#include <cuda_runtime.h>
#include <cuda_fp16.h>
#include <cstdint>

// Problem constants
#define S_DIM 256
#define B_DIM 128
#define D_DIM 768
#define L_DIM 200
#define V_DIM 8
#define M_DIM (S_DIM * B_DIM)   // 32768
#define N_DIM (L_DIM * V_DIM)   // 1600

// GEMM tiling
#define BM 128                  // rows per CTA (== one s; local row == batch b)
#define BN 64                   // cols per CTA (8 whole labels)
#define KC 64                   // fp16 k per chunk -> 128-byte rows (SW128-style)
#define NCHUNK (D_DIM / KC)     // 12

#define A_BYTES (BM * KC * 2)   // 16384
#define B_BYTES (BN * KC * 2)   //  8192
#define BUF_BYTES (A_BYTES + B_BYTES)
#define SMEM_TOTAL (2 * BUF_BYTES)   // 49152 (double buffered)

// Unit-normalized fp16 copies (no runtime allocation allowed)
__device__ __half g_A[(size_t)M_DIM * D_DIM];   // ~50 MB
__device__ __half g_B[(size_t)N_DIM * D_DIM];   // ~2.4 MB

// ---------------- PTX helpers (ALL base-PTX, no sm_103a-gated features) ----
__device__ __forceinline__ uint32_t smem_u32(const void* p) {
    uint32_t a;
    asm("{ .reg .u64 t; cvta.to.shared.u64 t, %1; cvt.u32.u64 %0, t; }"
        : "=r"(a) : "l"(p));
    return a;
}

#define CP_ASYNC16(s, g) \
    asm volatile("cp.async.cg.shared.global [%0], [%1], 16;" \
                 :: "r"(s), "l"(g) : "memory")
#define CP_COMMIT() asm volatile("cp.async.commit_group;" ::: "memory")
#define CP_WAIT(n)  asm volatile("cp.async.wait_group %0;" :: "n"(n) : "memory")

#define LDMATRIX_X4(r, addr) \
    asm volatile("ldmatrix.sync.aligned.m8n8.x4.shared.b16 {%0,%1,%2,%3}, [%4];" \
                 : "=r"((r)[0]), "=r"((r)[1]), "=r"((r)[2]), "=r"((r)[3]) \
                 : "r"(addr))

#define MMA16816(d, a, b0, b1) \
    asm volatile("mma.sync.aligned.m16n8k16.row.col.f32.f16.f16.f32 " \
                 "{%0,%1,%2,%3}, {%4,%5,%6,%7}, {%8,%9}, {%0,%1,%2,%3};" \
                 : "+f"((d)[0]), "+f"((d)[1]), "+f"((d)[2]), "+f"((d)[3]) \
                 : "r"((a)[0]), "r"((a)[1]), "r"((a)[2]), "r"((a)[3]), \
                   "r"(b0), "r"(b1))

// Sign-aware float atomic max (out initialized to -1.0; values in [-1, 1])
__device__ __forceinline__ void atomicMaxF(float* addr, float v) {
    if (v >= 0.0f) atomicMax((int*)addr, __float_as_int(v));
    else           atomicMin((unsigned int*)addr, __float_as_uint(v));
}

// Swizzled byte offset inside a tile: row r (128B rows), 16B chunk c in 0..7
__device__ __forceinline__ uint32_t swz(int r, int c) {
    return (uint32_t)(r * 128 + ((c ^ (r & 7)) << 4));
}

// ---------------- aux kernels ----------------
__global__ void init_out_kernel(float* out) {
    int i = blockIdx.x * blockDim.x + threadIdx.x;
    if (i < B_DIM * L_DIM) out[i] = -1.0f;
}

// One warp per row: fp32 -> unit-norm fp16 (norms ~27.7, eps clamp never active)
__global__ void normalize_kernel(const float* __restrict__ x,
                                 __half* __restrict__ y, int rows) {
    int w = (blockIdx.x * blockDim.x + threadIdx.x) >> 5;
    int lane = threadIdx.x & 31;
    if (w >= rows) return;
    const float4* p = reinterpret_cast<const float4*>(x + (size_t)w * D_DIM);
    float4 v[6];
    float s = 0.0f;
#pragma unroll
    for (int j = 0; j < 6; j++) {
        v[j] = p[lane + 32 * j];
        s += v[j].x * v[j].x + v[j].y * v[j].y + v[j].z * v[j].z + v[j].w * v[j].w;
    }
#pragma unroll
    for (int o = 16; o > 0; o >>= 1) s += __shfl_xor_sync(0xffffffffu, s, o);
    float inv = 1.0f / sqrtf(s);
#pragma unroll
    for (int j = 0; j < 6; j++) {
        __half2 h0 = __floats2half2_rn(v[j].x * inv, v[j].y * inv);
        __half2 h1 = __floats2half2_rn(v[j].z * inv, v[j].w * inv);
        size_t base = (size_t)w * D_DIM + (size_t)(lane + 32 * j) * 4;
        *reinterpret_cast<__half2*>(y + base)     = h0;
        *reinterpret_cast<__half2*>(y + base + 2) = h1;
    }
}

// ---------------- fused HMMA GEMM + max epilogue ----------------
// C[128 x 64] tile of cos = unitA(128 rows) . unitB(64 rows)^T, then
// max over v within each label, atomicMax into out[b][l].
__global__ __launch_bounds__(256, 2)
void gemm_mma_kernel(const __half* __restrict__ A, const __half* __restrict__ Bm,
                     float* __restrict__ out) {
    extern __shared__ char smem[];
    const uint32_t sb = smem_u32(smem);
    const int tid = threadIdx.x;
    const int wid = tid >> 5;
    const int lane = tid & 31;
    const int wm = wid >> 1;            // 0..3  (m: 32-row slab)
    const int wn = wid & 1;             // 0..1  (n: 32-col slab)
    const int m0 = blockIdx.y * BM;
    const int n0 = blockIdx.x * BN;
    const int l0 = blockIdx.x * (BN / V_DIM);

    auto loadA = [&](int buf, int c) {
#pragma unroll
        for (int j = 0; j < 4; j++) {
            int f = j * 256 + tid;                 // 0..1023
            int r = f >> 3, cc = f & 7;
            const __half* g = A + (size_t)(m0 + r) * D_DIM + c * KC + cc * 8;
            CP_ASYNC16(sb + buf * BUF_BYTES + swz(r, cc), g);
        }
    };
    auto loadB = [&](int buf, int c) {
#pragma unroll
        for (int j = 0; j < 2; j++) {
            int f = j * 256 + tid;                 // 0..511
            int r = f >> 3, cc = f & 7;
            const __half* g = Bm + (size_t)(n0 + r) * D_DIM + c * KC + cc * 8;
            CP_ASYNC16(sb + buf * BUF_BYTES + A_BYTES + swz(r, cc), g);
        }
    };

    float acc[2][4][4];
#pragma unroll
    for (int mi = 0; mi < 2; mi++)
#pragma unroll
        for (int ni = 0; ni < 4; ni++)
#pragma unroll
            for (int e = 0; e < 4; e++) acc[mi][ni][e] = 0.0f;

    loadA(0, 0); loadB(0, 0); CP_COMMIT();

    const int t = lane >> 3;            // ldmatrix tile index 0..3
    const int lr = lane & 7;            // row within 8-row tile

    for (int c = 0; c < NCHUNK; c++) {
        const int buf = c & 1;
        if (c + 1 < NCHUNK) {
            loadA(buf ^ 1, c + 1); loadB(buf ^ 1, c + 1); CP_COMMIT();
            CP_WAIT(1);
        } else {
            CP_WAIT(0);
        }
        __syncthreads();

        const uint32_t ab = sb + buf * BUF_BYTES;
        const uint32_t bb = ab + A_BYTES;
#pragma unroll
        for (int ks = 0; ks < 4; ks++) {          // four k16 steps per chunk
            uint32_t afr[2][4], bfr[2][4];
#pragma unroll
            for (int mi = 0; mi < 2; mi++) {
                // tiles: t0 rows0-7/k0-7, t1 rows8-15/k0-7, t2 rows0-7/k8-15, t3 rows8-15/k8-15
                int r = wm * 32 + mi * 16 + lr + ((t & 1) << 3);
                int cc = ks * 2 + (t >> 1);
                LDMATRIX_X4(afr[mi], ab + swz(r, cc));
            }
#pragma unroll
            for (int p = 0; p < 2; p++) {
                // tiles: t0 n0-7/k0-7, t1 n0-7/k8-15, t2 n8-15/k0-7, t3 n8-15/k8-15
                int r = wn * 32 + p * 16 + lr + ((t >> 1) << 3);
                int cc = ks * 2 + (t & 1);
                LDMATRIX_X4(bfr[p], bb + swz(r, cc));
            }
#pragma unroll
            for (int mi = 0; mi < 2; mi++)
#pragma unroll
                for (int ni = 0; ni < 4; ni++)
                    MMA16816(acc[mi][ni], afr[mi],
                             bfr[ni >> 1][(ni & 1) * 2], bfr[ni >> 1][(ni & 1) * 2 + 1]);
        }
        __syncthreads();   // protect buf before next iteration's cp.async overwrite
    }

    // ---- epilogue: each n8 fragment == one label (v pairs per thread) ----
    const int g  = lane >> 2;           // fragment row group 0..7
    const int tq = lane & 3;            // v-pair owner 0..3
#pragma unroll
    for (int mi = 0; mi < 2; mi++) {
        const int b0 = wm * 32 + mi * 16 + g;     // local row == batch b
#pragma unroll
        for (int ni = 0; ni < 4; ni++) {
            float mx0 = fmaxf(acc[mi][ni][0], acc[mi][ni][1]);   // row b0,  v=2tq,2tq+1
            float mx1 = fmaxf(acc[mi][ni][2], acc[mi][ni][3]);   // row b0+8
#pragma unroll
            for (int o = 1; o < 4; o <<= 1) {     // reduce over 4-lane group (all 8 v)
                mx0 = fmaxf(mx0, __shfl_xor_sync(0xffffffffu, mx0, o));
                mx1 = fmaxf(mx1, __shfl_xor_sync(0xffffffffu, mx1, o));
            }
            if (tq == 0) {
                int l = l0 + wn * 4 + ni;
                atomicMaxF(out + b0 * L_DIM + l, mx0);
                atomicMaxF(out + (b0 + 8) * L_DIM + l, mx1);
            }
        }
    }
}

extern "C" void kernel_launch(void* const* d_in, const int* in_sizes, int n_in,
                              void* d_out, int out_size) {
    const float* embed = (const float*)d_in[0];   // [256,128,768]
    const float* label = (const float*)d_in[1];   // [200,8,768]
    float* out = (float*)d_out;                   // [128,200]

    __half *d_A, *d_B;
    cudaGetSymbolAddress((void**)&d_A, g_A);
    cudaGetSymbolAddress((void**)&d_B, g_B);

    cudaFuncSetAttribute(gemm_mma_kernel,
                         cudaFuncAttributeMaxDynamicSharedMemorySize, SMEM_TOTAL);

    init_out_kernel<<<(B_DIM * L_DIM + 255) / 256, 256>>>(out);
    normalize_kernel<<<M_DIM / 8, 256>>>(embed, d_A, M_DIM);   // 8 warps/block
    normalize_kernel<<<N_DIM / 8, 256>>>(label, d_B, N_DIM);

    dim3 grid(N_DIM / BN, M_DIM / BM);   // (25, 256) = 6400 CTAs
    gemm_mma_kernel<<<grid, 256, SMEM_TOTAL>>>(d_A, d_B, out);
}